// round 13
// baseline (speedup 1.0000x reference)
#include <cuda_runtime.h>
#include <cuda_fp16.h>
#include <cstdint>

#define DINL __device__ __forceinline__

namespace {
constexpr int KDIM = 4096;
constexpr int NOUT = 4096;
constexpr int MTOK = 1024;

constexpr int BM = 64;        // CTA tile M
constexpr int BN = 128;       // CTA tile N
constexpr int BK = 64;        // K bytes per stage (int8)
constexpr int NUM_K = KDIM / BK;   // 64
constexpr int STAGES = 3;
constexpr int THREADS = 256;  // 8 warps: 2 in M x 4 in N (32x32 per warp)

constexpr int ROW_B = 80;     // 64 int8 + 16 pad -> conflict-free ldmatrix
constexpr int A_BYTES = BM * ROW_B;          // 5120 (per q array)
constexpr int B_BYTES = BN * ROW_B;          // 10240
constexpr int STAGE_BYTES = 2 * A_BYTES + B_BYTES;  // 20480 (q1, q2, B)
constexpr int SMEM_TOTAL = STAGES * STAGE_BYTES;    // 61440 -> 2 CTAs/SM

constexpr int QUANT_BLOCKS = (MTOK * KDIM / 16) / 256;   // 1024
constexpr int WPACK_BLOCKS = (NOUT * (KDIM / 256)) / 8;  // 8192
}  // namespace

// Scratch (static device globals: allowed; no runtime allocation).
__device__ __align__(16) int8_t g_q1[(size_t)MTOK * KDIM];   // 4 MB
__device__ __align__(16) int8_t g_q2[(size_t)MTOK * KDIM];   // 4 MB
__device__ __align__(16) int8_t g_wb[(size_t)KDIM * NOUT];   // 16.8 MB, chunk-major {0,1}
__device__ float g_s1[MTOK];                                 // per-token scale

DINL uint32_t smem_u32(const void* p) {
    uint32_t a;
    asm("{ .reg .u64 t; cvta.to.shared.u64 t, %1; cvt.u32.u64 %0, t; }" : "=r"(a) : "l"(p));
    return a;
}

// ---------------- prepass 1: per-token max |x| -> scale s1 ----------------
__global__ void __launch_bounds__(128) rowmax_kernel(const float* __restrict__ x) {
    const int row = blockIdx.x;
    const int t = threadIdx.x;
    const float4* p = (const float4*)(x + (size_t)row * KDIM);
    float m = 0.0f;
    #pragma unroll
    for (int i = 0; i < 8; ++i) {
        float4 v = p[t + 128 * i];
        m = fmaxf(m, fmaxf(fmaxf(fabsf(v.x), fabsf(v.y)), fmaxf(fabsf(v.z), fabsf(v.w))));
    }
    #pragma unroll
    for (int off = 16; off > 0; off >>= 1)
        m = fmaxf(m, __shfl_xor_sync(0xFFFFFFFFu, m, off));
    __shared__ float red[4];
    if ((t & 31) == 0) red[t >> 5] = m;
    __syncthreads();
    if (t == 0) {
        m = fmaxf(fmaxf(red[0], red[1]), fmaxf(red[2], red[3]));
        g_s1[row] = fmaxf(m, 1e-30f) / 127.0f;
    }
}

// ---------------- prepass 2: quantize x (hi/lo int8) + binarize W -> int8 {0,1} ----------------
__global__ void __launch_bounds__(256) prepass2_kernel(const float* __restrict__ x,
                                                       const float* __restrict__ w) {
    if (blockIdx.x < QUANT_BLOCKS) {
        int base = (blockIdx.x * 256 + threadIdx.x) * 16;   // 16 values/thread, one row
        int row = base >> 12;
        float s1 = g_s1[row];
        float inv = 1.0f / s1;
        float inv2 = inv * 128.0f;
        const float4* src = (const float4*)(x + base);
        uint32_t p1[4], p2[4];
        #pragma unroll
        for (int j = 0; j < 4; ++j) {
            float4 v = __ldcs(src + j);
            int a0 = max(-127, min(127, __float2int_rn(v.x * inv)));
            int a1 = max(-127, min(127, __float2int_rn(v.y * inv)));
            int a2 = max(-127, min(127, __float2int_rn(v.z * inv)));
            int a3 = max(-127, min(127, __float2int_rn(v.w * inv)));
            int b0 = __float2int_rn((v.x - a0 * s1) * inv2);
            int b1 = __float2int_rn((v.y - a1 * s1) * inv2);
            int b2 = __float2int_rn((v.z - a2 * s1) * inv2);
            int b3 = __float2int_rn((v.w - a3 * s1) * inv2);
            p1[j] = (a0 & 0xFF) | ((a1 & 0xFF) << 8) | ((a2 & 0xFF) << 16) | ((a3 & 0xFF) << 24);
            p2[j] = (b0 & 0xFF) | ((b1 & 0xFF) << 8) | ((b2 & 0xFF) << 16) | ((b3 & 0xFF) << 24);
        }
        *(uint4*)(g_q1 + base) = make_uint4(p1[0], p1[1], p1[2], p1[3]);
        *(uint4*)(g_q2 + base) = make_uint4(p2[0], p2[1], p2[2], p2[3]);
    } else {
        // one warp binarizes 256 K-values of one W row -> int8 {0,1}, chunk-major
        int pb = blockIdx.x - QUANT_BLOCKS;
        int lane = threadIdx.x & 31;
        int wg = pb * 8 + (threadIdx.x >> 5);
        int n = wg & (NOUT - 1);
        int kb = wg >> 12;                      // 256-wide K block, 0..15
        const float4* src = (const float4*)(w + (size_t)n * KDIM + kb * 256);
        #pragma unroll
        for (int half = 0; half < 2; ++half) {
            const float4 v = __ldcs(src + half * 32 + lane);
            uint32_t u = (v.x > 0.f ? 1u : 0u) | (v.y > 0.f ? 0x100u : 0u)
                       | (v.z > 0.f ? 0x10000u : 0u) | (v.w > 0.f ? 0x1000000u : 0u);
            int kloc = half * 128 + lane * 4;
            int c = kb * 4 + (kloc >> 6);       // BK=64 chunk index
            int kk = kloc & 63;
            *(uint32_t*)(g_wb + ((size_t)c * NOUT + n) * BK + kk) = u;
        }
    }
}

// ---------------- main GEMM: out = s1[m] * (q1@Wb + q2@Wb/128) * round(max(s,1)) ----------------
// int8 IMMA m16n8k32, exact s32 accumulation, no promotion. 8 warps (32x32 tile), 2 CTAs/SM.
__global__ void __launch_bounds__(THREADS, 2)
SBNLinear_39754217292616_kernel(const float* __restrict__ s, float* __restrict__ out) {
    extern __shared__ char smem[];
    const uint32_t sb = smem_u32(smem);
    const int tid = threadIdx.x;
    const int lane = tid & 31;
    const int wid = tid >> 5;                // 0..7
    const int m0 = blockIdx.x * BM;
    const int n0 = blockIdx.y * BN;
    const int m_off = (wid >> 2) * 32;       // 2 warps in M, 32 rows each
    const int n_off = (wid & 3) * 32;        // 4 warps in N, 32 cols each

    int acc1[2][4][4], acc2[2][4][4];
    #pragma unroll
    for (int mi = 0; mi < 2; ++mi)
        #pragma unroll
        for (int nj = 0; nj < 4; ++nj)
            #pragma unroll
            for (int e = 0; e < 4; ++e) { acc1[mi][nj][e] = 0; acc2[mi][nj][e] = 0; }

    // stage: [A1 64x80][A2 64x80][B 128x80]
    auto issueStage = [&](int c, int buf) {
        uint32_t st = sb + buf * STAGE_BYTES;
        {   // A1, A2: 64 rows x 4 x 16B = 256 each -> 1 cp.async per thread per array
            int row = tid >> 2;
            int ch = tid & 3;
            const int8_t* s1p = g_q1 + (size_t)(m0 + row) * KDIM + c * BK + ch * 16;
            const int8_t* s2p = g_q2 + (size_t)(m0 + row) * KDIM + c * BK + ch * 16;
            uint32_t d = row * ROW_B + ch * 16;
            asm volatile("cp.async.cg.shared.global [%0], [%1], 16;\n" :: "r"(st + d), "l"(s1p) : "memory");
            asm volatile("cp.async.cg.shared.global [%0], [%1], 16;\n" :: "r"(st + A_BYTES + d), "l"(s2p) : "memory");
        }
        {   // B: 128 rows x 4 x 16B = 512 -> 2 per thread
            #pragma unroll
            for (int i = 0; i < 2; ++i) {
                int idx = tid + i * THREADS;
                int row = idx >> 2;
                int ch = idx & 3;
                const int8_t* sp = g_wb + ((size_t)c * NOUT + n0 + row) * BK + ch * 16;
                uint32_t d = st + 2 * A_BYTES + row * ROW_B + ch * 16;
                asm volatile("cp.async.cg.shared.global [%0], [%1], 16;\n" :: "r"(d), "l"(sp) : "memory");
            }
        }
    };

    #pragma unroll
    for (int c = 0; c < STAGES - 1; ++c) {
        issueStage(c, c);
        asm volatile("cp.async.commit_group;\n" ::: "memory");
    }

    for (int c = 0; c < NUM_K; ++c) {
        const int buf = c % 3;
        if (c < NUM_K - 2) asm volatile("cp.async.wait_group 1;\n" ::: "memory");
        else               asm volatile("cp.async.wait_group 0;\n" ::: "memory");
        __syncthreads();

        const int cn = c + 2;
        if (cn < NUM_K) {
            issueStage(cn, cn % 3);
            asm volatile("cp.async.commit_group;\n" ::: "memory");
        }

        const uint32_t a1b = sb + buf * STAGE_BYTES;
        const uint32_t a2b = a1b + A_BYTES;
        const uint32_t bbb = a1b + 2 * A_BYTES;

        #pragma unroll
        for (int ks = 0; ks < 2; ++ks) {     // two k32 steps per 64-byte chunk
            uint32_t a1[2][4], a2[2][4], bf[4][2];
            // A fragments (m16 x k32): ldmatrix.x4 on 16B granules
            #pragma unroll
            for (int mi = 0; mi < 2; ++mi) {
                uint32_t addr1 = a1b + (uint32_t)(m_off + 16 * mi + (lane & 15)) * ROW_B
                                     + (uint32_t)(lane >> 4) * 16 + ks * 32;
                asm volatile("ldmatrix.sync.aligned.m8n8.x4.shared.b16 {%0,%1,%2,%3}, [%4];\n"
                             : "=r"(a1[mi][0]), "=r"(a1[mi][1]), "=r"(a1[mi][2]), "=r"(a1[mi][3])
                             : "r"(addr1));
                uint32_t addr2 = a2b + (uint32_t)(m_off + 16 * mi + (lane & 15)) * ROW_B
                                     + (uint32_t)(lane >> 4) * 16 + ks * 32;
                asm volatile("ldmatrix.sync.aligned.m8n8.x4.shared.b16 {%0,%1,%2,%3}, [%4];\n"
                             : "=r"(a2[mi][0]), "=r"(a2[mi][1]), "=r"(a2[mi][2]), "=r"(a2[mi][3])
                             : "r"(addr2));
            }
            // B fragments (k32 x n8): ldmatrix.x2
            #pragma unroll
            for (int nj = 0; nj < 4; ++nj) {
                uint32_t addr = bbb + (uint32_t)(n_off + 8 * nj + (lane & 7)) * ROW_B
                                    + (uint32_t)((lane >> 3) & 1) * 16 + ks * 32;
                asm volatile("ldmatrix.sync.aligned.m8n8.x2.shared.b16 {%0,%1}, [%2];\n"
                             : "=r"(bf[nj][0]), "=r"(bf[nj][1]) : "r"(addr));
            }
            #pragma unroll
            for (int nj = 0; nj < 4; ++nj)
                #pragma unroll
                for (int mi = 0; mi < 2; ++mi) {
                    asm volatile(
                        "mma.sync.aligned.m16n8k32.row.col.s32.s8.s8.s32 "
                        "{%0,%1,%2,%3}, {%4,%5,%6,%7}, {%8,%9}, {%0,%1,%2,%3};\n"
                        : "+r"(acc1[mi][nj][0]), "+r"(acc1[mi][nj][1]),
                          "+r"(acc1[mi][nj][2]), "+r"(acc1[mi][nj][3])
                        : "r"(a1[mi][0]), "r"(a1[mi][1]), "r"(a1[mi][2]), "r"(a1[mi][3]),
                          "r"(bf[nj][0]), "r"(bf[nj][1]));
                    asm volatile(
                        "mma.sync.aligned.m16n8k32.row.col.s32.s8.s8.s32 "
                        "{%0,%1,%2,%3}, {%4,%5,%6,%7}, {%8,%9}, {%0,%1,%2,%3};\n"
                        : "+r"(acc2[mi][nj][0]), "+r"(acc2[mi][nj][1]),
                          "+r"(acc2[mi][nj][2]), "+r"(acc2[mi][nj][3])
                        : "r"(a2[mi][0]), "r"(a2[mi][1]), "r"(a2[mi][2]), "r"(a2[mi][3]),
                          "r"(bf[nj][0]), "r"(bf[nj][1]));
                }
        }
    }

    // epilogue: out = s1[m] * (acc1 + acc2/128) * rint(max(s,1))
    float sc[4][2];
    #pragma unroll
    for (int nj = 0; nj < 4; ++nj) {
        int col = n0 + n_off + 8 * nj + 2 * (lane & 3);
        sc[nj][0] = rintf(fmaxf(s[col], 1.0f));
        sc[nj][1] = rintf(fmaxf(s[col + 1], 1.0f));
    }
    #pragma unroll
    for (int mi = 0; mi < 2; ++mi) {
        int r0 = m0 + m_off + 16 * mi + (lane >> 2);
        float sA = g_s1[r0];
        float sB = g_s1[r0 + 8];
        #pragma unroll
        for (int nj = 0; nj < 4; ++nj) {
            int col = n0 + n_off + 8 * nj + 2 * (lane & 3);
            float f0 = ((float)acc1[mi][nj][0] + 0.0078125f * (float)acc2[mi][nj][0]) * sA;
            float f1 = ((float)acc1[mi][nj][1] + 0.0078125f * (float)acc2[mi][nj][1]) * sA;
            float f2 = ((float)acc1[mi][nj][2] + 0.0078125f * (float)acc2[mi][nj][2]) * sB;
            float f3 = ((float)acc1[mi][nj][3] + 0.0078125f * (float)acc2[mi][nj][3]) * sB;
            *(float2*)(out + (size_t)r0 * NOUT + col) = make_float2(f0 * sc[nj][0], f1 * sc[nj][1]);
            *(float2*)(out + (size_t)(r0 + 8) * NOUT + col) = make_float2(f2 * sc[nj][0], f3 * sc[nj][1]);
        }
    }
}

extern "C" void kernel_launch(void* const* d_in, const int* in_sizes, int n_in,
                              void* d_out, int out_size) {
    (void)in_sizes; (void)n_in; (void)out_size;
    const float* x = (const float*)d_in[0];
    const float* w = (const float*)d_in[1];
    const float* s = (const float*)d_in[2];
    float* out = (float*)d_out;

    rowmax_kernel<<<MTOK, 128>>>(x);
    prepass2_kernel<<<QUANT_BLOCKS + WPACK_BLOCKS, 256>>>(x, w);

    cudaFuncSetAttribute(SBNLinear_39754217292616_kernel,
                         cudaFuncAttributeMaxDynamicSharedMemorySize, SMEM_TOTAL);
    dim3 grid(MTOK / BM, NOUT / BN);   // 16 x 32 = 512 CTAs, 2 resident/SM
    SBNLinear_39754217292616_kernel<<<grid, THREADS, SMEM_TOTAL>>>(s, out);
}

// round 14
// speedup vs baseline: 4.0778x; 4.0778x over previous
#include <cuda_runtime.h>
#include <cuda_fp16.h>
#include <cstdint>

#define DINL __device__ __forceinline__

namespace {
constexpr int KDIM = 4096;   // in_features
constexpr int NOUT = 4096;   // out_features
constexpr int MTOK = 1024;   // tokens

constexpr int BM = 128;      // CTA tile M
constexpr int BN = 128;      // CTA tile N
constexpr int BK = 64;       // K per stage (chunk)
constexpr int NUM_K = KDIM / BK;   // 64
constexpr int STAGES = 3;
constexpr int THREADS = 128; // 4 warps: 2 in M x 2 in N (64x64 per warp)

constexpr int A_ROW_B = 144;                // 64 halves (128B) + 16B pad -> conflict-free ldmatrix
constexpr int B_ROW_B = 144;
constexpr int A_BYTES = BM * A_ROW_B;       // 18432
constexpr int B_BYTES = BN * B_ROW_B;       // 18432
constexpr int STAGE_BYTES = A_BYTES + B_BYTES;   // 36864
constexpr int LUT_BYTES = 4096;                  // 256 x uint4 (byte -> 8 fp16 {0,1})
constexpr int SMEM_TOTAL = LUT_BYTES + STAGES * STAGE_BYTES;  // 114688 -> 2 CTAs/SM

constexpr int CONV_BLOCKS = (MTOK * KDIM / 16) / 256;           // 1024  (4 float4/thread)
constexpr int PACK_BLOCKS = (NOUT * (KDIM / 256)) / 8;          // 8192  (1 warp = 256 K-values)
}  // namespace

// Scratch (static device globals: allowed; no runtime allocation).
__device__ __align__(16) __half   g_xh[(size_t)MTOK * KDIM];          // 8 MB fp16 x
__device__ __align__(16) unsigned g_wbits[(KDIM / 32) * NOUT];        // 2 MB packed binarized W, [kword][n]

DINL uint32_t smem_u32(const void* p) {
    uint32_t a;
    asm("{ .reg .u64 t; cvta.to.shared.u64 t, %1; cvt.u32.u64 %0, t; }" : "=r"(a) : "l"(p));
    return a;
}

// ---------------- fused prepass: x->fp16  +  binarize/bit-pack W ----------------
__global__ void __launch_bounds__(256) prepass_kernel(const float* __restrict__ x,
                                                      const float* __restrict__ w) {
    if (blockIdx.x < CONV_BLOCKS) {
        // 4 independent float4 per thread (MLP=4)
        int base = blockIdx.x * 256 + threadIdx.x;
        float4 v[4];
        #pragma unroll
        for (int j = 0; j < 4; ++j)
            v[j] = __ldcs((const float4*)x + base + j * (CONV_BLOCKS * 256));
        #pragma unroll
        for (int j = 0; j < 4; ++j) {
            __half2 h0 = __floats2half2_rn(v[j].x, v[j].y);
            __half2 h1 = __floats2half2_rn(v[j].z, v[j].w);
            uint2 u;
            u.x = *(const uint32_t*)&h0;
            u.y = *(const uint32_t*)&h1;
            *(uint2*)(&g_xh[(size_t)(base + j * (CONV_BLOCKS * 256)) * 4]) = u;
        }
    } else {
        // one warp packs 256 K-values (2x float4/lane) of one W row into 8 bit-words
        int pb = blockIdx.x - CONV_BLOCKS;
        int lane = threadIdx.x & 31;
        int wg = pb * 8 + (threadIdx.x >> 5);   // global warp id
        int n = wg & (NOUT - 1);
        int kb = wg >> 12;                      // 256-wide K block, 0..15
        const float4* src = (const float4*)(w + (size_t)n * KDIM + kb * 256);
        const float4 v0 = __ldcs(src + lane);
        const float4 v1 = __ldcs(src + 32 + lane);
        #pragma unroll
        for (int half = 0; half < 2; ++half) {
            const float4& v = half ? v1 : v0;
            unsigned nib = (v.x > 0.f ? 1u : 0u) | (v.y > 0.f ? 2u : 0u)
                         | (v.z > 0.f ? 4u : 0u) | (v.w > 0.f ? 8u : 0u);
            unsigned a = nib | (__shfl_down_sync(0xFFFFFFFFu, nib, 1) << 4);
            unsigned b = a   | (__shfl_down_sync(0xFFFFFFFFu, a, 2)   << 8);
            unsigned m = b   | (__shfl_down_sync(0xFFFFFFFFu, b, 4)   << 16);
            if ((lane & 7) == 0) {
                int c = kb * 8 + half * 4 + (lane >> 3);
                g_wbits[c * NOUT + n] = m;
            }
        }
    }
}

// ---------------- main GEMM: out = (x_fp16 @ Wb^T) * round(max(s,1)) ----------------
// f16-accumulate HMMA; fp32 promotion per 64-K segment via k8 identity MMA.
// B expanded from 1-bit packed form via a 256-entry smem LUT (byte -> 8 fp16).
__global__ void __launch_bounds__(THREADS, 2)
SBNLinear_39754217292616_kernel(const float* __restrict__ s, float* __restrict__ out) {
    extern __shared__ char smem[];
    const uint32_t sb = smem_u32(smem);          // LUT at [0, 4096)
    const uint32_t stg = sb + LUT_BYTES;         // stages at [4096, ...)
    const int tid = threadIdx.x;
    const int lane = tid & 31;
    const int wid = tid >> 5;                // 0..3
    const int m0 = blockIdx.x * BM;
    const int n0 = blockIdx.y * BN;
    const int m_off = (wid >> 1) * 64;       // 2 warps in M
    const int n_off = (wid & 1) * 64;        // 2 warps in N

    // build LUT: byte e -> 8 fp16 {0,1}
    #pragma unroll
    for (int e = tid; e < 256; e += THREADS) {
        uint4 v;
        v.x = (e & 1u   ? 0x3C00u : 0u) | (e & 2u   ? 0x3C000000u : 0u);
        v.y = (e & 4u   ? 0x3C00u : 0u) | (e & 8u   ? 0x3C000000u : 0u);
        v.z = (e & 16u  ? 0x3C00u : 0u) | (e & 32u  ? 0x3C000000u : 0u);
        v.w = (e & 64u  ? 0x3C00u : 0u) | (e & 128u ? 0x3C000000u : 0u);
        asm volatile("st.shared.v4.b32 [%0], {%1,%2,%3,%4};\n"
                     :: "r"(sb + e * 16), "r"(v.x), "r"(v.y), "r"(v.z), "r"(v.w) : "memory");
    }
    __syncthreads();

    // identity fragment (fp16 I8) for the k8 promotion MMA
    const int q = lane >> 2, p = lane & 3;
    const uint32_t idf = ((2 * p == q) ? 0x3C00u : 0u) | ((2 * p + 1 == q) ? 0x3C000000u : 0u);

    float acc32[4][8][4];
    #pragma unroll
    for (int mi = 0; mi < 4; ++mi)
        #pragma unroll
        for (int nj = 0; nj < 8; ++nj)
            #pragma unroll
            for (int e = 0; e < 4; ++e) acc32[mi][nj][e] = 0.0f;

    uint32_t acc16[4][4][2];   // one nj-half at a time
    #pragma unroll
    for (int mi = 0; mi < 4; ++mi)
        #pragma unroll
        for (int nj = 0; nj < 4; ++nj) { acc16[mi][nj][0] = 0u; acc16[mi][nj][1] = 0u; }

    auto issueA = [&](int c, int buf) {
        #pragma unroll
        for (int i = 0; i < 8; ++i) {
            int qx = tid + i * THREADS;          // 0..1023
            int row = qx >> 3;
            int ch = qx & 7;
            uint32_t dst = stg + buf * STAGE_BYTES + row * A_ROW_B + ch * 16;
            const __half* src = &g_xh[(size_t)(m0 + row) * KDIM + c * BK + ch * 8];
            asm volatile("cp.async.cg.shared.global [%0], [%1], 16;\n" :: "r"(dst), "l"(src) : "memory");
        }
    };
    // one thread per B row: 8 bytes -> 8 LUT gathers -> 128B of fp16 {0,1}
    auto stsB = [&](uint2 bits, int buf) {
        uint32_t dst = stg + buf * STAGE_BYTES + A_BYTES + tid * B_ROW_B;
        #pragma unroll
        for (int j = 0; j < 8; ++j) {
            unsigned b8 = ((j < 4 ? bits.x : bits.y) >> ((j & 3) * 8)) & 0xFFu;
            uint32_t r0, r1, r2, r3;
            asm volatile("ld.shared.v4.b32 {%0,%1,%2,%3}, [%4];\n"
                         : "=r"(r0), "=r"(r1), "=r"(r2), "=r"(r3) : "r"(sb + b8 * 16));
            asm volatile("st.shared.v4.b32 [%0], {%1,%2,%3,%4};\n"
                         :: "r"(dst + j * 16), "r"(r0), "r"(r1), "r"(r2), "r"(r3) : "memory");
        }
    };
    auto loadBits = [&](int c) -> uint2 {
        uint2 r;
        r.x = g_wbits[(2 * c) * NOUT + n0 + tid];
        r.y = g_wbits[(2 * c + 1) * NOUT + n0 + tid];
        return r;
    };

    // prologue: stages 0..1
    #pragma unroll
    for (int c = 0; c < STAGES - 1; ++c) {
        issueA(c, c);
        asm volatile("cp.async.commit_group;\n" ::: "memory");
        stsB(loadBits(c), c);
    }
    uint2 bits_next = loadBits(2);

    for (int c = 0; c < NUM_K; ++c) {
        const int buf = c % 3;
        if (c < NUM_K - 2) asm volatile("cp.async.wait_group 1;\n" ::: "memory");
        else               asm volatile("cp.async.wait_group 0;\n" ::: "memory");
        __syncthreads();

        const int cn = c + 2;
        if (cn < NUM_K) {
            const int nbuf = cn % 3;
            stsB(bits_next, nbuf);
            issueA(cn, nbuf);
            asm volatile("cp.async.commit_group;\n" ::: "memory");
            if (cn + 1 < NUM_K)
                bits_next = loadBits(cn + 1);
        }

        const uint32_t ab = stg + buf * STAGE_BYTES;
        const uint32_t bb = ab + A_BYTES;

        #pragma unroll
        for (int half = 0; half < 2; ++half) {
            #pragma unroll
            for (int h = 0; h < 4; ++h) {
                uint32_t a[4][4];
                #pragma unroll
                for (int mi = 0; mi < 4; ++mi) {
                    uint32_t addr = ab + (uint32_t)(m_off + 16 * mi + (lane & 15)) * A_ROW_B
                                       + (uint32_t)(2 * h + (lane >> 4)) * 16;
                    asm volatile("ldmatrix.sync.aligned.m8n8.x4.shared.b16 {%0,%1,%2,%3}, [%4];\n"
                                 : "=r"(a[mi][0]), "=r"(a[mi][1]), "=r"(a[mi][2]), "=r"(a[mi][3])
                                 : "r"(addr));
                }
                #pragma unroll
                for (int gl = 0; gl < 2; ++gl) {
                    int g = half * 2 + gl;
                    int row = n_off + 16 * g + ((lane >> 4) << 3) + (lane & 7);
                    uint32_t addr = bb + (uint32_t)row * B_ROW_B
                                       + (uint32_t)(2 * h + ((lane >> 3) & 1)) * 16;
                    uint32_t r0, r1, r2, r3;
                    asm volatile("ldmatrix.sync.aligned.m8n8.x4.shared.b16 {%0,%1,%2,%3}, [%4];\n"
                                 : "=r"(r0), "=r"(r1), "=r"(r2), "=r"(r3) : "r"(addr));
                    #pragma unroll
                    for (int mi = 0; mi < 4; ++mi) {
                        asm volatile(
                            "mma.sync.aligned.m16n8k16.row.col.f16.f16.f16.f16 "
                            "{%0,%1}, {%2,%3,%4,%5}, {%6,%7}, {%0,%1};\n"
                            : "+r"(acc16[mi][2 * gl][0]), "+r"(acc16[mi][2 * gl][1])
                            : "r"(a[mi][0]), "r"(a[mi][1]), "r"(a[mi][2]), "r"(a[mi][3]),
                              "r"(r0), "r"(r1));
                        asm volatile(
                            "mma.sync.aligned.m16n8k16.row.col.f16.f16.f16.f16 "
                            "{%0,%1}, {%2,%3,%4,%5}, {%6,%7}, {%0,%1};\n"
                            : "+r"(acc16[mi][2 * gl + 1][0]), "+r"(acc16[mi][2 * gl + 1][1])
                            : "r"(a[mi][0]), "r"(a[mi][1]), "r"(a[mi][2]), "r"(a[mi][3]),
                              "r"(r2), "r"(r3));
                    }
                }
            }
            // promote this half's 64-K segment into fp32 (tensor pipe, k8 identity)
            #pragma unroll
            for (int mi = 0; mi < 4; ++mi)
                #pragma unroll
                for (int njl = 0; njl < 4; ++njl) {
                    int nj = half * 4 + njl;
                    asm volatile(
                        "mma.sync.aligned.m16n8k8.row.col.f32.f16.f16.f32 "
                        "{%0,%1,%2,%3}, {%4,%5}, {%6}, {%0,%1,%2,%3};\n"
                        : "+f"(acc32[mi][nj][0]), "+f"(acc32[mi][nj][1]),
                          "+f"(acc32[mi][nj][2]), "+f"(acc32[mi][nj][3])
                        : "r"(acc16[mi][njl][0]), "r"(acc16[mi][njl][1]), "r"(idf));
                    acc16[mi][njl][0] = 0u;
                    acc16[mi][njl][1] = 0u;
                }
        }
    }

    // epilogue: fuse s_eff = rint(max(s,1)) and store
    float sc[8][2];
    #pragma unroll
    for (int nj = 0; nj < 8; ++nj) {
        int col = n0 + n_off + 8 * nj + 2 * (lane & 3);
        sc[nj][0] = rintf(fmaxf(s[col], 1.0f));
        sc[nj][1] = rintf(fmaxf(s[col + 1], 1.0f));
    }
    #pragma unroll
    for (int mi = 0; mi < 4; ++mi) {
        int r0 = m0 + m_off + 16 * mi + (lane >> 2);
        #pragma unroll
        for (int nj = 0; nj < 8; ++nj) {
            int col = n0 + n_off + 8 * nj + 2 * (lane & 3);
            float2 v0 = make_float2(acc32[mi][nj][0] * sc[nj][0], acc32[mi][nj][1] * sc[nj][1]);
            float2 v1 = make_float2(acc32[mi][nj][2] * sc[nj][0], acc32[mi][nj][3] * sc[nj][1]);
            *(float2*)(out + (size_t)r0 * NOUT + col) = v0;
            *(float2*)(out + (size_t)(r0 + 8) * NOUT + col) = v1;
        }
    }
}

extern "C" void kernel_launch(void* const* d_in, const int* in_sizes, int n_in,
                              void* d_out, int out_size) {
    (void)in_sizes; (void)n_in; (void)out_size;
    const float* x = (const float*)d_in[0];
    const float* w = (const float*)d_in[1];
    const float* s = (const float*)d_in[2];
    float* out = (float*)d_out;

    prepass_kernel<<<CONV_BLOCKS + PACK_BLOCKS, 256>>>(x, w);

    cudaFuncSetAttribute(SBNLinear_39754217292616_kernel,
                         cudaFuncAttributeMaxDynamicSharedMemorySize, SMEM_TOTAL);
    dim3 grid(MTOK / BM, NOUT / BN);   // 8 x 32 = 256 CTAs, 2 resident/SM
    SBNLinear_39754217292616_kernel<<<grid, THREADS, SMEM_TOTAL>>>(s, out);
}